// round 1
// baseline (speedup 1.0000x reference)
#include <cuda_runtime.h>

#define VOCAB 87429
#define EDIM  51
#define EP    52          // padded embedding width (float4-friendly)
#define CCH   39
#define HTOK  8192
#define NJ    38          // total weight vectors across branches: 1+2+5+10+20
#define NJP   40          // padded
#define TH    128         // h-tile per block in k1
#define NBH   (HTOK / TH) // 64
#define NCZ   3           // channel chunks
#define CPZ   13          // channels per chunk (39 = 3*13)

// scratch (device globals — no allocation allowed)
__device__ float        g_embp[VOCAB * EP];          // padded embedding, ~18.2 MB
__device__ float        g_wpk [CCH * NJP * EP];      // packed weights [c][j][e]
__device__ float        g_A   [NCZ * HTOK * NJP];    // partial projections per c-chunk
__device__ unsigned int g_max5[5];

// ---------------------------------------------------------------------------
// kernel 0a: pad embedding table 51 -> 52 floats/row so gathers are float4
// ---------------------------------------------------------------------------
__global__ void kpad_emb(const float* __restrict__ emb) {
    int idx = blockIdx.x * blockDim.x + threadIdx.x;
    if (idx >= VOCAB * EP) return;
    int r = idx / EP;
    int e = idx - r * EP;
    g_embp[idx] = (e < EDIM) ? emb[r * EDIM + e] : 0.0f;
}

// ---------------------------------------------------------------------------
// kernel 0b: pack all branch conv weights into [c][j][e] padded layout
//   j mapping: br0 k=1 -> j 0; br1 k=2 -> j 1..2; br2 k=5 -> j 3..7;
//              br3 k=10 -> j 8..17; br4 k=20 -> j 18..37; j 38,39 zero pad.
// ---------------------------------------------------------------------------
__global__ void kpack_w(const float* __restrict__ w0, const float* __restrict__ w1,
                        const float* __restrict__ w2, const float* __restrict__ w3,
                        const float* __restrict__ w4) {
    int idx = blockIdx.x * blockDim.x + threadIdx.x;
    if (idx >= CCH * NJP * EP) return;
    int c   = idx / (NJP * EP);
    int rem = idx - c * (NJP * EP);
    int j   = rem / EP;
    int e   = rem - j * EP;
    float v = 0.0f;
    if (j < NJ && e < EDIM) {
        const float* wp; int kk, dk;
        if      (j < 1)  { wp = w0; kk = 1;  dk = j; }
        else if (j < 3)  { wp = w1; kk = 2;  dk = j - 1; }
        else if (j < 8)  { wp = w2; kk = 5;  dk = j - 3; }
        else if (j < 18) { wp = w3; kk = 10; dk = j - 8; }
        else             { wp = w4; kk = 20; dk = j - 18; }
        v = wp[(c * kk + dk) * EDIM + e];
    }
    g_wpk[idx] = v;
}

// ---------------------------------------------------------------------------
// kernel 1: A_z[h][j] = sum_{c in chunk z} emb[tok[c,h]] . W[c][j]
//   grid (64, 3), 320 threads. Register tile 4h x 4j per thread.
//   Tile strides (h: +32, j: +10) picked for low LDS bank conflicts.
// ---------------------------------------------------------------------------
__global__ __launch_bounds__(320, 1) void k1_dots(const int* __restrict__ tokens) {
    __shared__ float s_emb[TH * EP];    // 128*52*4 = 26624 B
    __shared__ float s_w  [NJP * EP];   // 40*52*4  =  8320 B

    const int tid  = threadIdx.x;
    const int h0   = blockIdx.x * TH;
    const int z    = blockIdx.y;
    const int cbeg = z * CPZ;

    if (blockIdx.x == 0 && z == 0 && tid < 5) g_max5[tid] = 0u;  // k2 runs after k1

    const int u = tid / 10;        // 0..31 : base h within tile
    const int v = tid - u * 10;    // 0..9  : base j

    float acc[4][4];
    #pragma unroll
    for (int i = 0; i < 4; i++)
        #pragma unroll
        for (int j = 0; j < 4; j++) acc[i][j] = 0.0f;

    for (int cc = 0; cc < CPZ; cc++) {
        const int c = cbeg + cc;

        // stage packed weights for this channel (520 float4)
        {
            const float4* src = (const float4*)&g_wpk[c * NJP * EP];
            float4* dst = (float4*)s_w;
            for (int idx = tid; idx < NJP * EP / 4; idx += 320)
                dst[idx] = src[idx];
        }
        // stage 128 embedding rows (2 threads/row, 13 float4 per row)
        if (tid < 256) {
            const int row  = tid >> 1;
            const int half = tid & 1;
            const int t    = tokens[c * HTOK + h0 + row];
            const float4* src = (const float4*)&g_embp[t * EP];
            float4* dst = (float4*)&s_emb[row * EP];
            #pragma unroll
            for (int q = 0; q < 7; q++) {
                int f = half * 7 + q;
                if (f < 13) dst[f] = src[f];
            }
        }
        __syncthreads();

        #pragma unroll
        for (int e4 = 0; e4 < 13; e4++) {
            float4 ev[4], wv[4];
            #pragma unroll
            for (int i = 0; i < 4; i++)
                ev[i] = *(const float4*)&s_emb[(u + 32 * i) * EP + e4 * 4];
            #pragma unroll
            for (int j = 0; j < 4; j++)
                wv[j] = *(const float4*)&s_w[(v + 10 * j) * EP + e4 * 4];
            #pragma unroll
            for (int i = 0; i < 4; i++)
                #pragma unroll
                for (int j = 0; j < 4; j++)
                    acc[i][j] += ev[i].x * wv[j].x + ev[i].y * wv[j].y
                               + ev[i].z * wv[j].z + ev[i].w * wv[j].w;
        }
        __syncthreads();
    }

    float* Az = &g_A[z * HTOK * NJP];
    #pragma unroll
    for (int i = 0; i < 4; i++)
        #pragma unroll
        for (int j = 0; j < 4; j++)
            Az[(h0 + u + 32 * i) * NJP + (v + 10 * j)] = acc[i][j];
}

// ---------------------------------------------------------------------------
// kernel 2: per-branch global max of relu(conv+b)
//   block of 256 h; stage A rows (incl. 19-row halo, 3 chunk slices summed)
//   into smem, per-thread tap sums, block max, atomicMax (nonneg float-as-uint).
// ---------------------------------------------------------------------------
#define K2T    256
#define K2ROWS (K2T + 19)   // 275
__global__ void k2_branch(const float* __restrict__ b0, const float* __restrict__ b1,
                          const float* __restrict__ b2, const float* __restrict__ b3,
                          const float* __restrict__ b4) {
    __shared__ float sA[K2ROWS * NJP];   // 44000 B
    __shared__ unsigned int sm[5];
    const int tid = threadIdx.x;
    const int h0  = blockIdx.x * K2T;

    if (tid < 5) sm[tid] = 0u;

    for (int idx = tid; idx < K2ROWS * NJP; idx += K2T) {
        int hh = idx / NJP;
        int gh = h0 + hh;
        float vsum = 0.0f;
        if (gh < HTOK) {
            int o = gh * NJP + (idx - hh * NJP);
            vsum = g_A[o] + g_A[HTOK * NJP + o] + g_A[2 * HTOK * NJP + o];
        }
        sA[idx] = vsum;
    }
    __syncthreads();

    const int h = h0 + tid;
    const float* r = &sA[tid * NJP];
    float y0 = r[0];
    float y1 = r[1] + r[NJP + 2];
    float y2 = 0.0f, y3 = 0.0f, y4 = 0.0f;
    #pragma unroll
    for (int d = 0; d < 5;  d++) y2 += r[d * NJP + 3  + d];
    #pragma unroll
    for (int d = 0; d < 10; d++) y3 += r[d * NJP + 8  + d];
    #pragma unroll
    for (int d = 0; d < 20; d++) y4 += r[d * NJP + 18 + d];

    float v0 =                      fmaxf(0.0f, y0 + *b0);
    float v1 = (h <= HTOK - 2)  ? fmaxf(0.0f, y1 + *b1) : 0.0f;
    float v2 = (h <= HTOK - 5)  ? fmaxf(0.0f, y2 + *b2) : 0.0f;
    float v3 = (h <= HTOK - 10) ? fmaxf(0.0f, y3 + *b3) : 0.0f;
    float v4 = (h <= HTOK - 20) ? fmaxf(0.0f, y4 + *b4) : 0.0f;

    atomicMax(&sm[0], __float_as_uint(v0));
    atomicMax(&sm[1], __float_as_uint(v1));
    atomicMax(&sm[2], __float_as_uint(v2));
    atomicMax(&sm[3], __float_as_uint(v3));
    atomicMax(&sm[4], __float_as_uint(v4));
    __syncthreads();
    if (tid < 5) atomicMax(&g_max5[tid], sm[tid]);
}

// ---------------------------------------------------------------------------
// kernel 3: 5 -> 8 linear, relu, softmax -> out[8]
// ---------------------------------------------------------------------------
__global__ void k3_head(const float* __restrict__ lin_w, const float* __restrict__ lin_b,
                        float* __restrict__ out) {
    if (threadIdx.x != 0 || blockIdx.x != 0) return;
    float f[5];
    #pragma unroll
    for (int i = 0; i < 5; i++) f[i] = __uint_as_float(g_max5[i]);
    float lg[8], mx = -1e30f;
    #pragma unroll
    for (int o = 0; o < 8; o++) {
        float s = lin_b[o];
        #pragma unroll
        for (int i = 0; i < 5; i++) s += lin_w[o * 5 + i] * f[i];
        s = fmaxf(s, 0.0f);
        lg[o] = s;
        mx = fmaxf(mx, s);
    }
    float den = 0.0f;
    #pragma unroll
    for (int o = 0; o < 8; o++) { lg[o] = expf(lg[o] - mx); den += lg[o]; }
    #pragma unroll
    for (int o = 0; o < 8; o++) out[o] = lg[o] / den;
}

// ---------------------------------------------------------------------------
extern "C" void kernel_launch(void* const* d_in, const int* in_sizes, int n_in,
                              void* d_out, int out_size) {
    const int*   tokens = (const int*)  d_in[0];
    const float* emb    = (const float*)d_in[1];
    const float* lin_w  = (const float*)d_in[2];
    const float* lin_b  = (const float*)d_in[3];
    const float* w0     = (const float*)d_in[4];
    const float* b0     = (const float*)d_in[5];
    const float* w1     = (const float*)d_in[6];
    const float* b1     = (const float*)d_in[7];
    const float* w2     = (const float*)d_in[8];
    const float* b2     = (const float*)d_in[9];
    const float* w3     = (const float*)d_in[10];
    const float* b3     = (const float*)d_in[11];
    const float* w4     = (const float*)d_in[12];
    const float* b4     = (const float*)d_in[13];
    float* out = (float*)d_out;

    kpad_emb<<<(VOCAB * EP + 255) / 256, 256>>>(emb);
    kpack_w <<<(CCH * NJP * EP + 255) / 256, 256>>>(w0, w1, w2, w3, w4);
    k1_dots <<<dim3(NBH, NCZ), 320>>>(tokens);
    k2_branch<<<HTOK / K2T, K2T>>>(b0, b1, b2, b3, b4);
    k3_head <<<1, 32>>>(lin_w, lin_b, out);
}

// round 2
// speedup vs baseline: 1.6421x; 1.6421x over previous
#include <cuda_runtime.h>

#define VOCAB 87429
#define EDIM  51
#define EP    52          // padded embedding width (13 float4)
#define CCH   39
#define HTOK  8192
#define NJ    38          // 1+2+5+10+20 weight vectors
#define NJP   40          // padded
#define TH    128         // h-tile per block in k1
#define NBH   (HTOK / TH) // 64
#define NCZ   4           // channel chunks: 10,10,10,9
#define SLC   (HTOK * NJP)

// scratch (device globals — no allocation allowed)
__device__ float        g_embp[VOCAB * EP];       // padded embedding ~18.2 MB
__device__ float        g_wpk [CCH * NJP * EP];   // packed weights [c][j][e]
__device__ float        g_A   [NCZ * SLC];        // partial projections, layout [z][j][h]
__device__ unsigned int g_max5[5];

__device__ __forceinline__ void fma2(unsigned long long& d,
                                     unsigned long long a,
                                     unsigned long long b) {
    asm("fma.rn.f32x2 %0, %1, %2, %0;" : "+l"(d) : "l"(a), "l"(b));
}

// ---------------------------------------------------------------------------
// kernel 0a: pad embedding table 51 -> 52 floats/row (float4-friendly gathers)
// ---------------------------------------------------------------------------
__global__ void kpad_emb(const float* __restrict__ emb) {
    int idx = blockIdx.x * blockDim.x + threadIdx.x;
    if (idx >= VOCAB * EP) return;
    int r = idx / EP;
    int e = idx - r * EP;
    g_embp[idx] = (e < EDIM) ? emb[r * EDIM + e] : 0.0f;
}

// ---------------------------------------------------------------------------
// kernel 0b: pack branch conv weights into [c][j][e] padded layout
//   j: br0 -> 0; br1 -> 1..2; br2 -> 3..7; br3 -> 8..17; br4 -> 18..37
// ---------------------------------------------------------------------------
__global__ void kpack_w(const float* __restrict__ w0, const float* __restrict__ w1,
                        const float* __restrict__ w2, const float* __restrict__ w3,
                        const float* __restrict__ w4) {
    int idx = blockIdx.x * blockDim.x + threadIdx.x;
    if (idx >= CCH * NJP * EP) return;
    int c   = idx / (NJP * EP);
    int rem = idx - c * (NJP * EP);
    int j   = rem / EP;
    int e   = rem - j * EP;
    float v = 0.0f;
    if (j < NJ && e < EDIM) {
        const float* wp; int kk, dk;
        if      (j < 1)  { wp = w0; kk = 1;  dk = j; }
        else if (j < 3)  { wp = w1; kk = 2;  dk = j - 1; }
        else if (j < 8)  { wp = w2; kk = 5;  dk = j - 3; }
        else if (j < 18) { wp = w3; kk = 10; dk = j - 8; }
        else             { wp = w4; kk = 20; dk = j - 18; }
        v = wp[(c * kk + dk) * EDIM + e];
    }
    g_wpk[idx] = v;
}

// ---------------------------------------------------------------------------
// kernel 1: A_z[j][h] = sum_{c in chunk z} emb[tok[c,h]] . W[c][j]
//   128 threads, 8h x 5j register tile per thread, fma.rn.f32x2 accumulation.
//   u = tid>>3 (16 h-groups), v = tid&7 (8 j-groups):
//     ev loads: 8-way broadcast, 4 addrs -> banks {0-3,20-23,8-11,28-31}
//     wv loads: 4-way broadcast, 8 addrs -> all 32 banks once.   Conflict-free.
// ---------------------------------------------------------------------------
__global__ __launch_bounds__(128, 2) void k1_dots(const int* __restrict__ tokens) {
    __shared__ float s_emb[TH * EP];    // 26624 B
    __shared__ float s_w  [NJP * EP];   //  8320 B

    const int tid  = threadIdx.x;
    const int h0   = blockIdx.x * TH;
    const int z    = blockIdx.y;
    const int cbeg = z * 10;
    const int cend = (cbeg + 10 < CCH) ? cbeg + 10 : CCH;

    if (blockIdx.x == 0 && z == 0 && tid < 5) g_max5[tid] = 0u;  // k2 runs after

    const int u = tid >> 3;   // 0..15
    const int v = tid & 7;    // 0..7

    unsigned long long acc[8][5];
    #pragma unroll
    for (int i = 0; i < 8; i++)
        #pragma unroll
        for (int j = 0; j < 5; j++) acc[i][j] = 0ull;

    for (int c = cbeg; c < cend; c++) {
        // stage this channel's packed weights (520 float4)
        {
            const float4* src = (const float4*)&g_wpk[c * NJP * EP];
            float4* dst = (float4*)s_w;
            #pragma unroll
            for (int q = 0; q < 5; q++) {
                int idx = tid + q * 128;
                if (idx < NJP * EP / 4) dst[idx] = src[idx];
            }
        }
        // stage 128 embedding rows (1 thread per row, 13 float4)
        {
            const int t = tokens[c * HTOK + h0 + tid];
            const float4* src = (const float4*)&g_embp[t * EP];
            float4* dst = (float4*)&s_emb[tid * EP];
            #pragma unroll
            for (int q = 0; q < 13; q++) dst[q] = src[q];
        }
        __syncthreads();

        #pragma unroll
        for (int e4 = 0; e4 < 13; e4++) {
            ulonglong2 ev[8], wv[5];
            #pragma unroll
            for (int i = 0; i < 8; i++)
                ev[i] = *(const ulonglong2*)&s_emb[(u + 16 * i) * EP + e4 * 4];
            #pragma unroll
            for (int j = 0; j < 5; j++)
                wv[j] = *(const ulonglong2*)&s_w[(v + 8 * j) * EP + e4 * 4];
            // two passes (x then y) so each acc's reuse distance is 40 instrs
            #pragma unroll
            for (int i = 0; i < 8; i++)
                #pragma unroll
                for (int j = 0; j < 5; j++)
                    fma2(acc[i][j], ev[i].x, wv[j].x);
            #pragma unroll
            for (int i = 0; i < 8; i++)
                #pragma unroll
                for (int j = 0; j < 5; j++)
                    fma2(acc[i][j], ev[i].y, wv[j].y);
        }
        __syncthreads();
    }

    // write transposed: A[z][j][h]
    float* Az = &g_A[z * SLC];
    #pragma unroll
    for (int i = 0; i < 8; i++)
        #pragma unroll
        for (int j = 0; j < 5; j++) {
            unsigned long long a = acc[i][j];
            float lo = __uint_as_float((unsigned)(a & 0xffffffffull));
            float hi = __uint_as_float((unsigned)(a >> 32));
            Az[(v + 8 * j) * HTOK + (h0 + u + 16 * i)] = lo + hi;
        }
}

// ---------------------------------------------------------------------------
// kernel 2: per-(h-block, branch) max of relu(conv+b). A is [z][j][h]:
//   taps are coalesced L2-resident loads; warp+block max; atomicMax.
// ---------------------------------------------------------------------------
__global__ void k2_branch(const float* __restrict__ b0, const float* __restrict__ b1,
                          const float* __restrict__ b2, const float* __restrict__ b3,
                          const float* __restrict__ b4) {
    __shared__ unsigned int sm;
    const int tid = threadIdx.x;
    const int br  = blockIdx.y;
    const int h   = blockIdx.x * 256 + tid;
    if (tid == 0) sm = 0u;
    __syncthreads();

    const int base[5] = {0, 1, 3, 8, 18};
    const int cnt [5] = {1, 2, 5, 10, 20};
    const int k = cnt[br];

    float val = 0.0f;
    if (h <= HTOK - k) {
        float y = 0.0f;
        int o = base[br] * HTOK + h;
        #pragma unroll 4
        for (int d = 0; d < k; d++, o += HTOK + 1)
            y += g_A[o] + g_A[SLC + o] + g_A[2 * SLC + o] + g_A[3 * SLC + o];
        const float* bp = (br == 0) ? b0 : (br == 1) ? b1 : (br == 2) ? b2
                        : (br == 3) ? b3 : b4;
        val = fmaxf(y + *bp, 0.0f);
    }
    #pragma unroll
    for (int off = 16; off; off >>= 1)
        val = fmaxf(val, __shfl_xor_sync(0xffffffffu, val, off));
    if ((tid & 31) == 0) atomicMax(&sm, __float_as_uint(val));
    __syncthreads();
    if (tid == 0) atomicMax(&g_max5[br], sm);
}

// ---------------------------------------------------------------------------
// kernel 3: 5 -> 8 linear, relu, softmax -> out[8]
// ---------------------------------------------------------------------------
__global__ void k3_head(const float* __restrict__ lin_w, const float* __restrict__ lin_b,
                        float* __restrict__ out) {
    if (threadIdx.x != 0 || blockIdx.x != 0) return;
    float f[5];
    #pragma unroll
    for (int i = 0; i < 5; i++) f[i] = __uint_as_float(g_max5[i]);
    float lg[8], mx = -1e30f;
    #pragma unroll
    for (int o = 0; o < 8; o++) {
        float s = lin_b[o];
        #pragma unroll
        for (int i = 0; i < 5; i++) s += lin_w[o * 5 + i] * f[i];
        s = fmaxf(s, 0.0f);
        lg[o] = s;
        mx = fmaxf(mx, s);
    }
    float den = 0.0f;
    #pragma unroll
    for (int o = 0; o < 8; o++) { lg[o] = expf(lg[o] - mx); den += lg[o]; }
    #pragma unroll
    for (int o = 0; o < 8; o++) out[o] = lg[o] / den;
}

// ---------------------------------------------------------------------------
extern "C" void kernel_launch(void* const* d_in, const int* in_sizes, int n_in,
                              void* d_out, int out_size) {
    const int*   tokens = (const int*)  d_in[0];
    const float* emb    = (const float*)d_in[1];
    const float* lin_w  = (const float*)d_in[2];
    const float* lin_b  = (const float*)d_in[3];
    const float* w0     = (const float*)d_in[4];
    const float* b0     = (const float*)d_in[5];
    const float* w1     = (const float*)d_in[6];
    const float* b1     = (const float*)d_in[7];
    const float* w2     = (const float*)d_in[8];
    const float* b2     = (const float*)d_in[9];
    const float* w3     = (const float*)d_in[10];
    const float* b3     = (const float*)d_in[11];
    const float* w4     = (const float*)d_in[12];
    const float* b4     = (const float*)d_in[13];
    float* out = (float*)d_out;

    kpad_emb<<<(VOCAB * EP + 255) / 256, 256>>>(emb);
    kpack_w <<<(CCH * NJP * EP + 255) / 256, 256>>>(w0, w1, w2, w3, w4);
    k1_dots <<<dim3(NBH, NCZ), 128>>>(tokens);
    k2_branch<<<dim3(HTOK / 256, 5), 256>>>(b0, b1, b2, b3, b4);
    k3_head <<<1, 32>>>(lin_w, lin_b, out);
}